// round 17
// baseline (speedup 1.0000x reference)
#include <cuda_runtime.h>
#include <math.h>

// Problem constants (B=1)
#define Lc     2048
#define Hc     16
#define Dc     64
#define Mc     24
#define Wc     128
#define CHUNK  128
#define NC     16
#define SCALEc 0.125f
#define EPSc   1e-4f
#define DN     0.35355339059327373f   // sqrt(0.125)
#define LN24   3.1780538303479458f    // log(24)
#define SCL2E  0.18033688011112042f   // 0.125 * log2(e)

typedef unsigned long long U64;

__device__ __forceinline__ U64 fma2(U64 a, U64 b, U64 c) {
    U64 d; asm("fma.rn.f32x2 %0, %1, %2, %3;" : "=l"(d) : "l"(a), "l"(b), "l"(c)); return d;
}
__device__ __forceinline__ U64 mul2(U64 a, U64 b) {
    U64 d; asm("mul.rn.f32x2 %0, %1, %2;" : "=l"(d) : "l"(a), "l"(b)); return d;
}
__device__ __forceinline__ U64 add2(U64 a, U64 b) {
    U64 d; asm("add.rn.f32x2 %0, %1, %2;" : "=l"(d) : "l"(a), "l"(b)); return d;
}
__device__ __forceinline__ U64 pack2(float x, float y) {
    U64 d; asm("mov.b64 %0, {%1,%2};" : "=l"(d)
               : "r"(__float_as_uint(x)), "r"(__float_as_uint(y))); return d;
}
__device__ __forceinline__ float hadd2(U64 a) {
    unsigned lo, hi; asm("mov.b64 {%0,%1}, %2;" : "=r"(lo), "=r"(hi) : "l"(a));
    return __uint_as_float(lo) + __uint_as_float(hi);
}
__device__ __forceinline__ void unpack2(float& x, float& y, U64 a) {
    unsigned lo, hi; asm("mov.b64 {%0,%1}, %2;" : "=r"(lo), "=r"(hi) : "l"(a));
    x = __uint_as_float(lo); y = __uint_as_float(hi);
}

#define CP_COMMIT() asm volatile("cp.async.commit_group;")
#define CP_WAIT(n)  asm volatile("cp.async.wait_group %0;" :: "n"(n))

// ---------------- scratch ----------------
__device__ float g_kprime[Hc * Lc * Mc];
__device__ float g_chunkmax[Hc * NC];
__device__ float g_psum [Hc * NC * Mc];
__device__ float g_pvsum[Hc * NC * Mc * Dc];
__device__ float g_vsum [Hc * NC * Dc];
__device__ unsigned g_cnt[Hc];
__device__ unsigned g_done[Hc];

// batched-load dot over full 64 dims: all 16 LDS.128 issued before any FMA
__device__ __forceinline__ float bdot64(const float* row, const U64* q2) {
    const ulonglong2* pr = (const ulonglong2*)row;
    ulonglong2 rr[16];
#pragma unroll
    for (int u = 0; u < 16; u++) rr[u] = pr[u];
    U64 a0 = mul2(q2[0], rr[0].x), a1 = mul2(q2[1], rr[0].y);
    U64 a2 = mul2(q2[2], rr[1].x), a3 = mul2(q2[3], rr[1].y);
#pragma unroll
    for (int u = 2; u < 16; u += 2) {
        a0 = fma2(q2[2*u],   rr[u].x,   a0);
        a1 = fma2(q2[2*u+1], rr[u].y,   a1);
        a2 = fma2(q2[2*u+2], rr[u+1].x, a2);
        a3 = fma2(q2[2*u+3], rr[u+1].y, a3);
    }
    return hadd2(add2(add2(a0, a1), add2(a2, a3)));
}

// batched-load variant: all 22 LDS issued before any dependent FMA
__device__ __forceinline__ void key_dots(const float* krow, const float* kprow,
                                         const U64* q2, const U64* qp2,
                                         float& sd, float& gp)
{
    const ulonglong2* kr = (const ulonglong2*)krow;
    const ulonglong2* pr = (const ulonglong2*)kprow;
    ulonglong2 kk[16];
#pragma unroll
    for (int u = 0; u < 16; u++) kk[u] = kr[u];
    ulonglong2 pp[6];
#pragma unroll
    for (int u = 0; u < 6; u++) pp[u] = pr[u];

    U64 a0 = mul2(q2[0], kk[0].x), a1 = mul2(q2[1], kk[0].y);
    U64 a2 = mul2(q2[2], kk[1].x), a3 = mul2(q2[3], kk[1].y);
#pragma unroll
    for (int u = 2; u < 16; u += 2) {
        a0 = fma2(q2[2*u],   kk[u].x,   a0);
        a1 = fma2(q2[2*u+1], kk[u].y,   a1);
        a2 = fma2(q2[2*u+2], kk[u+1].x, a2);
        a3 = fma2(q2[2*u+3], kk[u+1].y, a3);
    }
    sd = hadd2(add2(add2(a0, a1), add2(a2, a3)));

    U64 g0 = mul2(qp2[0], pp[0].x), g1 = mul2(qp2[1], pp[0].y);
    g0 = fma2(qp2[2],  pp[1].x, g0); g1 = fma2(qp2[3],  pp[1].y, g1);
    g0 = fma2(qp2[4],  pp[2].x, g0); g1 = fma2(qp2[5],  pp[2].y, g1);
    g0 = fma2(qp2[6],  pp[3].x, g0); g1 = fma2(qp2[7],  pp[3].y, g1);
    g0 = fma2(qp2[8],  pp[4].x, g0); g1 = fma2(qp2[9],  pp[4].y, g1);
    g0 = fma2(qp2[10], pp[5].x, g0); g1 = fma2(qp2[11], pp[5].y, g1);
    gp = hadd2(add2(g0, g1));
}

// ---------------- smem layout (shared by prep phase + main phase) ----------
#define OFF_K    0
#define OFF_KP   16384
#define OFF_KVB  22528
#define OFF_PROJ 24064
#define OFF_KB   25600
#define OFF_SV   25632
#define OFF_RING 25696
#define SM4_FLOATS 27744

__device__ __forceinline__ void vacc64(U64 c2, const float* vrow, U64* o2) {
    const ulonglong2* vr = (const ulonglong2*)vrow;
#pragma unroll
    for (int u = 0; u < 16; u++) {
        ulonglong2 x = vr[u];
        o2[2*u]   = fma2(c2, x.x, o2[2*u]);
        o2[2*u+1] = fma2(c2, x.y, o2[2*u+1]);
    }
}

__device__ __forceinline__ void stage2v(const float* __restrict__ qkv, int h,
                                        unsigned ringw_u32, int slot,
                                        int ra, int rb, int lane)
{
    int row = (lane < 16) ? ra : rb;
    const float* src = qkv + ((size_t)(row * 3 + 2) * Hc + h) * Dc + (lane & 15) * 4;
    unsigned dst = ringw_u32 + (unsigned)(slot * 512 + ((lane >> 4) * 256) + (lane & 15) * 16);
    asm volatile("cp.async.cg.shared.global [%0], [%1], 16;" :: "r"(dst), "l"(src));
}

// ---------------- fused kernel ----------------
__global__ void __launch_bounds__(128, 2) kfused(const float* __restrict__ qkv,
                                                 const float* __restrict__ proj,
                                                 float* __restrict__ out)
{
    extern __shared__ float sm[];
    float* K_s    = sm + OFF_K;
    float* kp_s   = sm + OFF_KP;     // main kp tile (stride 24)
    float* kvb_s  = sm + OFF_KVB;
    float* proj_s = sm + OFF_PROJ;
    float* kb_s   = sm + OFF_KB;
    float* sv_s   = sm + OFF_SV;     // also prep red4
    float* ring   = sm + OFF_RING;
    float* vbuf   = sm + OFF_K;      // prep V tile (overwritten by K later)

    const int c = blockIdx.x, h = blockIdx.y, t = threadIdx.x;
    const int warp = t >> 5, lane = t & 31;
    const int hc = h * NC + c;
    const int cstart = c * CHUNK;
    const int i = cstart + t;
    const int tilebase = (c > 0) ? (c - 1) * CHUNK : 0;
    const int nkeys    = (c > 0) ? 256 : 128;
    const int cb = (c > 0) ? 128 : 0;
    const int cbase = cb * Mc;           // current chunk's kp offset in kp_s

    // ================= PREP PHASE (chunk c of head h) =================
    for (int f = t; f < 384; f += 128)
        ((float4*)proj_s)[f] = ((const float4*)proj)[f];
    for (int f = t; f < 2048; f += 128) {
        int r = f >> 4, dv = f & 15;
        ((float4*)vbuf)[f] =
            ((const float4*)(qkv + ((size_t)((cstart + r) * 3 + 2) * Hc + h) * Dc))[dv];
    }
    __syncthreads();

    {
        U64 k2r[32];
        {
            const ulonglong2* kr = (const ulonglong2*)(qkv + ((size_t)((cstart + t) * 3 + 1) * Hc + h) * Dc);
#pragma unroll
            for (int u = 0; u < 16; u++) { ulonglong2 x = kr[u]; k2r[2*u] = x.x; k2r[2*u+1] = x.y; }
        }
        float xnk;
        {
            U64 a0 = mul2(k2r[0], k2r[0]), a1 = mul2(k2r[1], k2r[1]);
            U64 a2 = mul2(k2r[2], k2r[2]), a3 = mul2(k2r[3], k2r[3]);
#pragma unroll
            for (int u = 4; u < 32; u += 4) {
                a0 = fma2(k2r[u],   k2r[u],   a0);
                a1 = fma2(k2r[u+1], k2r[u+1], a1);
                a2 = fma2(k2r[u+2], k2r[u+2], a2);
                a3 = fma2(k2r[u+3], k2r[u+3], a3);
            }
            xnk = hadd2(add2(add2(a0, a1), add2(a2, a3))) * 0.0625f;
        }
        float xdk[Mc];
        float mx = -3.4e38f;
#pragma unroll
        for (int m = 0; m < Mc; m++) {
            xdk[m] = bdot64(proj_s + m * Dc, k2r) * DN;
            mx = fmaxf(mx, xdk[m]);
        }
#pragma unroll
        for (int off = 16; off > 0; off >>= 1)
            mx = fmaxf(mx, __shfl_xor_sync(0xffffffffu, mx, off));
        if ((t & 31) == 0) sv_s[t >> 5] = mx;   // red4
        __syncthreads();
        const float locmax = fmaxf(fmaxf(sv_s[0], sv_s[1]), fmaxf(sv_s[2], sv_s[3]));
        if (t == 0) g_chunkmax[hc] = locmax;

        // write kp directly into MAIN layout (stride 24, at current-chunk rows)
        float p[Mc];
#pragma unroll
        for (int m = 0; m < Mc; m++)
            p[m] = __expf(xdk[m] - xnk - locmax);
        {
            float4* kps = (float4*)(kp_s + cbase + t * Mc);
            float4* kpo = (float4*)(g_kprime + ((size_t)h * Lc + cstart + t) * Mc);
#pragma unroll
            for (int e = 0; e < 6; e++) {
                float4 v = make_float4(p[4*e], p[4*e+1], p[4*e+2], p[4*e+3]);
                kps[e] = v;
                kpo[e] = v;
            }
        }
        __syncthreads();

        // pvsum with f32x2 (reads kp from stride-24 smem, broadcast)
        U64* pvo2 = (U64*)(g_pvsum + (size_t)hc * Mc * Dc);
        const ulonglong2* vb2 = (const ulonglong2*)vbuf;
        const float* kpc = kp_s + cbase;
#pragma unroll
        for (int grp = 0; grp < 3; grp++) {
            int o = t + 128 * grp;
            int m = o >> 4, d4 = o & 15;
            U64 aX = 0ULL, aY = 0ULL, bX = 0ULL, bY = 0ULL;
            for (int row = 0; row < CHUNK; row += 2) {
                U64 kp0 = pack2(kpc[row * Mc + m],       kpc[row * Mc + m]);
                U64 kp1 = pack2(kpc[(row + 1) * Mc + m], kpc[(row + 1) * Mc + m]);
                ulonglong2 v0 = vb2[row * 16 + d4];
                ulonglong2 v1 = vb2[(row + 1) * 16 + d4];
                aX = fma2(kp0, v0.x, aX); aY = fma2(kp0, v0.y, aY);
                bX = fma2(kp1, v1.x, bX); bY = fma2(kp1, v1.y, bY);
            }
            pvo2[o * 2]     = add2(aX, bX);
            pvo2[o * 2 + 1] = add2(aY, bY);
        }
        if (t < Mc) {
            float a = 0.f;
            for (int row = 0; row < CHUNK; row++) a += kpc[row * Mc + t];
            g_psum[hc * Mc + t] = a;
        }
        if (t >= 32 && t < 48) {
            int t16 = t - 32;
            float4 a = make_float4(0.f, 0.f, 0.f, 0.f);
            for (int row = 0; row < CHUNK; row++) {
                float4 v = ((const float4*)vbuf)[row * 16 + t16];
                a.x += v.x; a.y += v.y; a.z += v.z; a.w += v.w;
            }
            ((float4*)(g_vsum + (size_t)hc * Dc))[t16] = a;
        }
    }
    __threadfence();
    __syncthreads();
    if (t == 0) atomicAdd(&g_cnt[h], 1u);

    // ================= MAIN PHASE A (independent of other CTAs) =========
    for (int f = t; f < nkeys * 16; f += 128) {
        int r = f >> 4, dv = f & 15;
        ((float4*)K_s)[r * 16 + dv] =
            ((const float4*)(qkv + ((size_t)((tilebase + r) * 3 + 1) * Hc + h) * Dc))[dv];
    }

    U64 q2[32];
    {
        const ulonglong2* qr = (const ulonglong2*)(qkv + ((size_t)(i * 3) * Hc + h) * Dc);
#pragma unroll
        for (int u = 0; u < 16; u++) { ulonglong2 x = qr[u]; q2[2*u] = x.x; q2[2*u+1] = x.y; }
    }
    float xn;
    {
        U64 a0 = mul2(q2[0], q2[0]), a1 = mul2(q2[1], q2[1]);
        U64 a2 = mul2(q2[2], q2[2]), a3 = mul2(q2[3], q2[3]);
#pragma unroll
        for (int u = 4; u < 32; u += 4) {
            a0 = fma2(q2[u],   q2[u],   a0);
            a1 = fma2(q2[u+1], q2[u+1], a1);
            a2 = fma2(q2[u+2], q2[u+2], a2);
            a3 = fma2(q2[u+3], q2[u+3], a3);
        }
        xn = hadd2(add2(add2(a0, a1), add2(a2, a3))) * 0.0625f;
    }
    float xd[Mc];
    float qstab = -3.4e38f;
#pragma unroll
    for (int m = 0; m < Mc; m++) {
        xd[m] = bdot64(proj_s + m * Dc, q2) * DN;
        qstab = fmaxf(qstab, xd[m]);
    }
    U64 qp2[12];
    float qpsum = 0.f;
#pragma unroll
    for (int e = 0; e < 12; e++) {
        float a = __expf(xd[2*e]   - qstab) + EPSc;
        float b = __expf(xd[2*e+1] - qstab) + EPSc;
        qp2[e] = pack2(a, b);
        qpsum += a + b;
    }
    const float epsqp = EPSc * qpsum;

    // ================= wait for all prep CTAs of this head =============
    if (t == 0) {
        unsigned v;
        do {
            asm volatile("ld.acquire.gpu.u32 %0, [%1];" : "=r"(v) : "l"(&g_cnt[h]) : "memory");
        } while (v < (unsigned)NC);
    }
    __syncthreads();
    // self-reset for next graph replay
    if (t == 0) {
        unsigned d = atomicAdd(&g_done[h], 1u);
        if (d == (unsigned)(NC - 1)) {
            g_done[h] = 0u;
            asm volatile("st.release.gpu.u32 [%0], %1;" :: "l"(&g_cnt[h]), "r"(0u) : "memory");
        }
    }

    // ================= MAIN PHASE B =====================================
    float alf[NC];
    float kstab;
    {
        float cm[NC];
        kstab = -3.4e38f;
#pragma unroll
        for (int cc = 0; cc < NC; cc++) {
            cm[cc] = g_chunkmax[h * NC + cc];
            kstab = fmaxf(kstab, cm[cc]);
        }
#pragma unroll
        for (int cc = 0; cc < NC; cc++) alf[cc] = __expf(cm[cc] - kstab);
    }
    const float alphaP = (c > 0) ? alf[c - 1] : 0.f;
    const float alphaC = alf[c];
    const float gs = qstab - xn + kstab - LN24;

    // load ONLY previous chunk's kp (current chunk already in smem)
    if (c > 0) {
        const float4* kpsrc = (const float4*)(g_kprime + ((size_t)h * Lc + tilebase) * Mc);
        for (int f = t; f < 128 * 6; f += 128) ((float4*)kp_s)[f] = kpsrc[f];
    }
#pragma unroll
    for (int g = 0; g < 3; g++) {
        int f = t + 128 * g;
        float4 a = make_float4(0.f, 0.f, 0.f, 0.f);
        for (int cc = 0; cc < c; cc++) {
            float al = alf[cc];
            float4 x = *((const float4*)g_pvsum + (size_t)(h * NC + cc) * 384 + f);
            a.x = fmaf(al, x.x, a.x); a.y = fmaf(al, x.y, a.y);
            a.z = fmaf(al, x.z, a.z); a.w = fmaf(al, x.w, a.w);
        }
        ((float4*)kvb_s)[f] = a;
    }
    if (t < Mc) {
        float a = (float)c * (CHUNK * EPSc);
        for (int cc = 0; cc < c; cc++)
            a = fmaf(alf[cc], g_psum[(h * NC + cc) * Mc + t], a);
        kb_s[t] = a;
    }
    if (t >= 64 && t < 80) {
        int t16 = t - 64;
        float4 a = make_float4(0.f, 0.f, 0.f, 0.f);
        for (int cc = 0; cc < c; cc++) {
            float4 x = *((const float4*)(g_vsum + (size_t)(h * NC + cc) * Dc) + t16);
            a.x += x.x; a.y += x.y; a.z += x.z; a.w += x.w;
        }
        ((float4*)sv_s)[t16] = a;
    }
    __syncthreads();

    float kbdot = 0.f;
#pragma unroll
    for (int e = 0; e < 12; e++) {
        float a, b; unpack2(a, b, qp2[e]);
        kbdot = fmaf(a, kb_s[2*e],     kbdot);
        kbdot = fmaf(b, kb_s[2*e + 1], kbdot);
    }

    // ---- pass 1: Z, Asc; batched LDS per key; cache (exp(s), g_eff) ----
    __align__(16) float2 sg[160];
    int idx = 0;
    float Z = 0.f, AscP = 0.f, AscC = 0.f;
    const int j0 = 32 * warp;
    if (c > 0) {
#pragma unroll 1
        for (int jr = j0; jr < 128; jr++) {
            float sd, gp;
            key_dots(K_s + jr * Dc, kp_s + jr * Mc, q2, qp2, sd, gp);
            float geff = fmaf(alphaP, gp, epsqp);
            float es = (jr >= t) ? exp2f(sd * SCL2E) : 0.f;
            float gg = (jr >= t) ? geff : 0.f;
            Z += es; AscP += gg;
            sg[idx++] = make_float2(es, gg);
        }
    }
    {
        const int jend = j0 + 32;
#pragma unroll 1
        for (int jc = 0; jc < jend; jc++) {
            float sd, gp;
            key_dots(K_s + (cb + jc) * Dc, kp_s + (cb + jc) * Mc, q2, qp2, sd, gp);
            float geff = fmaf(alphaC, gp, epsqp);
            float es = (jc <= t) ? exp2f(sd * SCL2E) : 0.f;
            float gg = (jc <= t) ? geff : 0.f;
            Z += es; AscC += gg;
            sg[idx++] = make_float2(es, gg);
        }
    }

    // ---- normalization scalars ----
    const float Asc = 0.875f * AscC - 0.125f * AscP;
    const float lse = __logf(Z);
    const float gln = __logf(fmaxf(kbdot + Asc, 1e-24f)) + gs;
    float a_ = fmaxf(lse, gln), b_ = fminf(lse, gln);
    const float lnorm = a_ + log1pf(__expf(b_ - a_));
    const float gps  = __expf(gs - lnorm);
    const float invZ = 1.f / Z;
    const float gpsP = -0.125f * gps;
    const float gpsC =  0.875f * gps;

    // ---- pass 2: V ring + sg prefetched one batch ahead ----
    U64 o2[32];
#pragma unroll
    for (int u = 0; u < 32; u++) o2[u] = 0ULL;

    const unsigned ringw_u32 =
        (unsigned)__cvta_generic_to_shared(ring + warp * 512);
    const float* ringw = ring + warp * 512;
    int idx2 = 0;

    const int nbat1 = (c > 0) ? ((128 - j0) >> 1) : 0;
    const int nbat2 = (j0 + 32) >> 1;
    const int nbtot = nbat1 + nbat2;

    ulonglong2 sgcur = *(const ulonglong2*)&sg[0];

    if (c > 0) {
#pragma unroll
        for (int p = 0; p < 3; p++) {
            int ra = j0 + 2*p;     if (ra > 127) ra = 127;
            int rb = j0 + 2*p + 1; if (rb > 127) rb = 127;
            stage2v(qkv, h, ringw_u32, p & 3, tilebase + ra, tilebase + rb, lane);
            CP_COMMIT();
        }
#pragma unroll 1
        for (int b = 0; b < nbat1; b++) {
            int sp = b + 3;
            int ra = j0 + 2*sp;     if (ra > 127) ra = 127;
            int rb = j0 + 2*sp + 1; if (rb > 127) rb = 127;
            stage2v(qkv, h, ringw_u32, sp & 3, tilebase + ra, tilebase + rb, lane);
            CP_COMMIT();
            int nidx = idx2 + 2; if (nidx > 2 * nbtot - 2) nidx = 2 * nbtot - 2;
            ulonglong2 sgnext = *(const ulonglong2*)&sg[nidx];
            CP_WAIT(3);
            __syncwarp();
            const float* vb = ringw + (b & 3) * 128;
            {
                float esv, ggv; unpack2(esv, ggv, sgcur.x);
                float coef = fmaf(invZ, esv, gpsP * ggv);
                vacc64(pack2(coef, coef), vb, o2);
            }
            {
                float esv, ggv; unpack2(esv, ggv, sgcur.y);
                float coef = fmaf(invZ, esv, gpsP * ggv);
                vacc64(pack2(coef, coef), vb + 64, o2);
            }
            sgcur = sgnext;
            idx2 += 2;
        }
        CP_WAIT(0);
        __syncwarp();
    }
    {
        const int jend = j0 + 32;
#pragma unroll
        for (int p = 0; p < 3; p++) {
            int ra = 2*p;     if (ra > jend - 1) ra = jend - 1;
            int rb = 2*p + 1; if (rb > jend - 1) rb = jend - 1;
            stage2v(qkv, h, ringw_u32, p & 3, cstart + ra, cstart + rb, lane);
            CP_COMMIT();
        }
#pragma unroll 1
        for (int b = 0; b < nbat2; b++) {
            int sp = b + 3;
            int ra = 2*sp;     if (ra > jend - 1) ra = jend - 1;
            int rb = 2*sp + 1; if (rb > jend - 1) rb = jend - 1;
            stage2v(qkv, h, ringw_u32, sp & 3, cstart + ra, cstart + rb, lane);
            CP_COMMIT();
            int nidx = idx2 + 2; if (nidx > 2 * nbtot - 2) nidx = 2 * nbtot - 2;
            ulonglong2 sgnext = *(const ulonglong2*)&sg[nidx];
            CP_WAIT(3);
            __syncwarp();
            const float* vb = ringw + (b & 3) * 128;
            {
                float esv, ggv; unpack2(esv, ggv, sgcur.x);
                float coef = fmaf(invZ, esv, gpsC * ggv);
                vacc64(pack2(coef, coef), vb, o2);
            }
            {
                float esv, ggv; unpack2(esv, ggv, sgcur.y);
                float coef = fmaf(invZ, esv, gpsC * ggv);
                vacc64(pack2(coef, coef), vb + 64, o2);
            }
            sgcur = sgnext;
            idx2 += 2;
        }
        CP_WAIT(0);
        __syncwarp();
    }

    // ---- epilogue: o += gps * (q' . KVbase_alpha) + gps*qpsum*EPS * sv ----
#pragma unroll
    for (int e = 0; e < 12; e++) {
        float qa, qb; unpack2(qa, qb, qp2[e]);
        U64 ca  = pack2(gps * qa, gps * qa);
        U64 cb2 = pack2(gps * qb, gps * qb);
        const ulonglong2* r0 = (const ulonglong2*)(kvb_s + (2*e) * Dc);
        const ulonglong2* r1 = (const ulonglong2*)(kvb_s + (2*e + 1) * Dc);
#pragma unroll
        for (int u = 0; u < 16; u++) {
            ulonglong2 x0 = r0[u];
            ulonglong2 x1 = r1[u];
            o2[2*u]   = fma2(ca,  x0.x, o2[2*u]);
            o2[2*u+1] = fma2(ca,  x0.y, o2[2*u+1]);
            o2[2*u]   = fma2(cb2, x1.x, o2[2*u]);
            o2[2*u+1] = fma2(cb2, x1.y, o2[2*u+1]);
        }
    }
    {
        float csv = gps * epsqp;
        U64 c2 = pack2(csv, csv);
        vacc64(c2, sv_s, o2);
    }

    ulonglong2* orow = (ulonglong2*)(out + ((size_t)i * Hc + h) * Dc);
#pragma unroll
    for (int u = 0; u < 16; u++) {
        ulonglong2 w2; w2.x = o2[2*u]; w2.y = o2[2*u+1];
        orow[u] = w2;
    }
}

// ---------------- launch ----------------
extern "C" void kernel_launch(void* const* d_in, const int* in_sizes, int n_in,
                              void* d_out, int out_size)
{
    (void)out_size;
    const float* qkv  = (const float*)d_in[0];
    const float* proj = (const float*)d_in[1];
    if (n_in >= 2 && in_sizes[0] < in_sizes[1]) {
        const float* tmp = qkv; qkv = proj; proj = tmp;
    }
    float* out = (float*)d_out;

    cudaFuncSetAttribute(kfused, cudaFuncAttributeMaxDynamicSharedMemorySize,
                         SM4_FLOATS * (int)sizeof(float));

    dim3 grid(NC, Hc);
    kfused<<<grid, 128, SM4_FLOATS * (int)sizeof(float)>>>(qkv, proj, out);
}